// round 1
// baseline (speedup 1.0000x reference)
#include <cuda_runtime.h>
#include <math.h>

#define N_NODES 8192
#define D_DIM   128
#define CAP     1024          // max nonzeros per row we track (E[nnz]=~83, binomial tail << CAP)
#define SCAN_THREADS 256

// scratch for per-node scores s[j] = emb[j] . H_v  (no cudaMalloc allowed)
__device__ float g_s[N_NODES];

// ---------------------------------------------------------------------------
// Kernel 1: s = emb @ H_v   (one warp per row)
// ---------------------------------------------------------------------------
__global__ void score_kernel(const float* __restrict__ emb,
                             const float* __restrict__ hv) {
    int warp = (blockIdx.x * blockDim.x + threadIdx.x) >> 5;
    int lane = threadIdx.x & 31;
    if (warp >= N_NODES) return;
    const float4* e = reinterpret_cast<const float4*>(emb + (size_t)warp * D_DIM);
    const float4* h = reinterpret_cast<const float4*>(hv);
    float4 a = e[lane];
    float4 b = h[lane];
    float d = a.x * b.x + a.y * b.y + a.z * b.z + a.w * b.w;
    #pragma unroll
    for (int off = 16; off > 0; off >>= 1)
        d += __shfl_xor_sync(0xFFFFFFFFu, d, off);
    if (lane == 0) g_s[warp] = d;
}

// ---------------------------------------------------------------------------
// Kernel 2: fused compaction + masked softmax + SpMM. One CTA per row.
// ---------------------------------------------------------------------------
__global__ __launch_bounds__(SCAN_THREADS)
void node_attn_kernel(const float* __restrict__ emb,
                      const float* __restrict__ adj,
                      float* __restrict__ out) {
    const int row = blockIdx.x;
    const int tid = threadIdx.x;

    __shared__ int   s_cnt;
    __shared__ float s_red[SCAN_THREADS];
    __shared__ float s_bcast;
    __shared__ int   s_cols[CAP];
    __shared__ float s_w[CAP];

    if (tid == 0) s_cnt = 0;
    __syncthreads();

    // ---- Phase 1: stream the adj row (streaming loads: don't pollute L2) ----
    const float4* rowp = reinterpret_cast<const float4*>(adj + (size_t)row * N_NODES);
    float lmax = -INFINITY;
    #pragma unroll
    for (int it = 0; it < N_NODES / 4 / SCAN_THREADS; it++) {   // 8 iterations
        int i = tid + it * SCAN_THREADS;
        float4 v = __ldcs(&rowp[i]);
        int c0 = 4 * i;
        float vv[4] = {v.x, v.y, v.z, v.w};
        #pragma unroll
        for (int l = 0; l < 4; l++) {
            if (vv[l] != 0.0f) {
                float lg = vv[l] * g_s[c0 + l];
                int idx = atomicAdd(&s_cnt, 1);
                if (idx < CAP) {
                    s_cols[idx] = c0 + l;
                    s_w[idx]    = lg;
                }
                lmax = fmaxf(lmax, lg);
            }
        }
    }

    // ---- block-reduce max ----
    s_red[tid] = lmax;
    __syncthreads();
    #pragma unroll
    for (int off = SCAN_THREADS / 2; off > 0; off >>= 1) {
        if (tid < off) s_red[tid] = fmaxf(s_red[tid], s_red[tid + off]);
        __syncthreads();
    }
    if (tid == 0) s_bcast = s_red[0];
    __syncthreads();
    const float maxv = s_bcast;
    int n = s_cnt;
    if (n > CAP) n = CAP;

    // ---- Phase 2: exp + sum ----
    float lsum = 0.0f;
    for (int k = tid; k < n; k += SCAN_THREADS) {
        float e = __expf(s_w[k] - maxv);
        s_w[k] = e;
        lsum += e;
    }
    s_red[tid] = lsum;
    __syncthreads();
    #pragma unroll
    for (int off = SCAN_THREADS / 2; off > 0; off >>= 1) {
        if (tid < off) s_red[tid] += s_red[tid + off];
        __syncthreads();
    }
    if (tid == 0) s_bcast = 1.0f / s_red[0];
    __syncthreads();
    const float inv = s_bcast;

    // ---- Phase 3: out[row, d] = inv * sum_k w_k * emb[col_k, d] ----
    // 256 threads cover 128 dims twice: thread t owns dim (t & 127),
    // handles k = (t>>7), (t>>7)+2, ... ; partial pairs combined via smem.
    {
        const int d    = tid & (D_DIM - 1);
        const int half = tid >> 7;            // 0 or 1
        float acc = 0.0f;
        for (int k = half; k < n; k += 2) {
            acc += s_w[k] * __ldg(&emb[(size_t)s_cols[k] * D_DIM + d]);
        }
        s_red[tid] = acc;
        __syncthreads();
        if (half == 0) {
            float r = (s_red[tid] + s_red[tid + 128]) * inv;
            out[(size_t)row * D_DIM + d] = r;
        }
    }
}

// ---------------------------------------------------------------------------
extern "C" void kernel_launch(void* const* d_in, const int* in_sizes, int n_in,
                              void* d_out, int out_size) {
    const float* emb = nullptr;
    const float* adj = nullptr;
    const float* hv  = nullptr;
    for (int i = 0; i < n_in; i++) {
        if (in_sizes[i] == N_NODES * D_DIM)           emb = (const float*)d_in[i];
        else if (in_sizes[i] == (long)N_NODES * N_NODES ? 0 : 0) {} // placeholder
    }
    // identify by exact element counts (robust to ordering)
    for (int i = 0; i < n_in; i++) {
        long sz = in_sizes[i];
        if (sz == (long)N_NODES * D_DIM)      emb = (const float*)d_in[i];
        else if (sz == D_DIM)                 hv  = (const float*)d_in[i];
        else                                  adj = (const float*)d_in[i];
    }
    float* out = (float*)d_out;

    score_kernel<<<N_NODES / 8, 256>>>(emb, hv);
    node_attn_kernel<<<N_NODES, SCAN_THREADS>>>(emb, adj, out);
}